// round 14
// baseline (speedup 1.0000x reference)
#include <cuda_runtime.h>
#include <cuda_fp16.h>
#include <cstdint>
#include <math.h>

#define B_SZ   4
#define LSEQ   2048
#define DMODEL 1024
#define DINNER 2048
#define DHALF  1024
#define DSTATE 16
#define DTRANK 64
#define XDBL_C 96
#define MROWS  (B_SZ * LSEQ)   // 8192

// ---------------- scratch (static device arrays; no allocation) ----------------
__device__ __half g_xh  [(size_t)MROWS * DMODEL];   // half(x)
__device__ float  g_xz  [(size_t)MROWS * DINNER];   // x @ W_in (float)
__device__ float  g_xs  [(size_t)MROWS * DHALF];    // silu(conv(xs)) float (scan u)
__device__ __half g_xsh [(size_t)MROWS * DHALF];    // same, half (GEMM3 A)
__device__ float  g_xdbl[(size_t)MROWS * XDBL_C];   // xs @ W_xdbl (float, scan B/C)
__device__ __half g_dth [(size_t)MROWS * DTRANK];   // half(xdbl[:, :64]) (dt GEMM A)
__device__ float  g_delta[(size_t)MROWS * DHALF];   // softplus(...)
__device__ __half g_cath[(size_t)MROWS * DINNER];   // [y | z] half (GEMM4 A)
__device__ __half g_WinTh [(size_t)DINNER * DMODEL];
__device__ __half g_WxTh  [(size_t)XDBL_C * DHALF];
__device__ __half g_WdtTh [(size_t)DHALF * DTRANK];
__device__ __half g_WoutTh[(size_t)DMODEL * DINNER];

// ================= helpers =================
__device__ __forceinline__ uint32_t smem_u32(const void* p) {
    uint32_t a;
    asm("{ .reg .u64 t; cvta.to.shared.u64 t, %1; cvt.u32.u64 %0, t; }" : "=r"(a) : "l"(p));
    return a;
}
__device__ __forceinline__ void cp16(uint32_t dst, const void* src) {
    asm volatile("cp.async.cg.shared.global [%0], [%1], 16;" :: "r"(dst), "l"(src));
}
#define CP_COMMIT() asm volatile("cp.async.commit_group;" ::: "memory")
#define CP_WAIT(n)  asm volatile("cp.async.wait_group %0;" :: "n"(n) : "memory")

__device__ __forceinline__ void ldsm4(uint32_t* r, uint32_t addr) {
    asm volatile("ldmatrix.sync.aligned.m8n8.x4.shared.b16 {%0,%1,%2,%3}, [%4];"
        : "=r"(r[0]), "=r"(r[1]), "=r"(r[2]), "=r"(r[3]) : "r"(addr));
}
__device__ __forceinline__ void mma_f16(float* c, const uint32_t* a, uint32_t b0, uint32_t b1) {
    asm volatile(
        "mma.sync.aligned.m16n8k16.row.col.f32.f16.f16.f32 "
        "{%0,%1,%2,%3}, {%4,%5,%6,%7}, {%8,%9}, {%0,%1,%2,%3};"
        : "+f"(c[0]), "+f"(c[1]), "+f"(c[2]), "+f"(c[3])
        : "r"(a[0]), "r"(a[1]), "r"(a[2]), "r"(a[3]), "r"(b0), "r"(b1));
}

// ---------------- epilogues ----------------
// 0: none; 1: +bias; 2: fast softplus(acc + 2*bias)
template <int EPI>
__device__ __forceinline__ float apply_epi(float acc, const float* __restrict__ bias, int col) {
    if (EPI == 1) return acc + bias[col];
    if (EPI == 2) {
        float v = acc + 2.0f * bias[col];
        return fmaxf(v, 0.0f) + __logf(1.0f + __expf(-fabsf(v)));  // MUFU-only softplus
    }
    return acc;
}

// ================= fp16 mma.sync GEMM =================
// C[M,N] = A[M,K] @ Bt[N,K]^T, half in, fp32 accum/out. CTA 128x128, BK=32,
// 256 thr, warp tile 64x32. 80B-padded smem rows; 3-stage cp.async.
#define HSTAGE 10240
#define HSM_TOTAL (6 * HSTAGE)

template <int EPI>
__global__ __launch_bounds__(256)
void gemm_mma(const __half* __restrict__ A, const __half* __restrict__ Bt,
              float* __restrict__ C, const float* __restrict__ bias,
              int M, int N, int K, int lda, int ldb, int ldc)
{
    extern __shared__ char smc[];
    const uint32_t sAu = smem_u32(smc);
    const uint32_t sBu = sAu + 3 * HSTAGE;

    const int tid = threadIdx.x;
    const int wid = tid >> 5, lane = tid & 31;
    const int g = lane >> 2, tg = lane & 3;
    const int wm = wid & 1, wn = wid >> 1;      // 2 x 4 warp grid
    const int row0 = blockIdx.y * 128;
    const int col0 = blockIdx.x * 128;

    float acc[4][4][4];
#pragma unroll
    for (int i = 0; i < 4; ++i)
#pragma unroll
        for (int j = 0; j < 4; ++j)
#pragma unroll
            for (int c = 0; c < 4; ++c) acc[i][j][c] = 0.0f;

    const int rm = tid >> 2, cc = tid & 3;
    auto load_stage = [&](int s, int kt) {
        const uint32_t ab = sAu + s * HSTAGE;
        const uint32_t bb = sBu + s * HSTAGE;
        const int k0 = kt * 32;
#pragma unroll
        for (int i = 0; i < 2; ++i) {
            int m = rm + i * 64;
            cp16(ab + m * 80 + cc * 16, A + (size_t)(row0 + m) * lda + k0 + cc * 8);
        }
#pragma unroll
        for (int i = 0; i < 2; ++i) {
            int n = rm + i * 64;
            if (col0 + n < N)
                cp16(bb + n * 80 + cc * 16, Bt + (size_t)(col0 + n) * ldb + k0 + cc * 8);
        }
    };

    const int KT = K >> 5;   // >= 2 for all our GEMMs
    load_stage(0, 0); CP_COMMIT();
    load_stage(1, 1); CP_COMMIT();

    const int lrow = (lane & 7) + (lane & 8);
    const int lhi  = (lane >> 4) & 1;
    const uint32_t aoffs = (uint32_t)((wm * 64 + lrow) * 80 + lhi * 16);
    const uint32_t boffs = (uint32_t)((wn * 32 + lrow) * 80 + lhi * 16);

    int s = 0, pf = 2;
    for (int kt = 0; kt < KT; ++kt) {
        if (kt + 2 < KT)      { load_stage(pf, kt + 2); CP_COMMIT(); CP_WAIT(2); }
        else if (kt + 1 < KT) { CP_WAIT(1); }
        else                  { CP_WAIT(0); }
        __syncthreads();

        const uint32_t abase = sAu + s * HSTAGE + aoffs;
        const uint32_t bbase = sBu + s * HSTAGE + boffs;
#pragma unroll
        for (int ks = 0; ks < 2; ++ks) {
            uint32_t af[4][4], bf[2][4];
#pragma unroll
            for (int mt = 0; mt < 4; ++mt)
                ldsm4(af[mt], abase + mt * (16 * 80) + ks * 32);
#pragma unroll
            for (int pr = 0; pr < 2; ++pr)
                ldsm4(bf[pr], bbase + pr * (16 * 80) + ks * 32);
#pragma unroll
            for (int mt = 0; mt < 4; ++mt)
#pragma unroll
                for (int nt = 0; nt < 4; ++nt)
                    mma_f16(acc[mt][nt], af[mt], bf[nt >> 1][nt & 1], bf[nt >> 1][2 + (nt & 1)]);
        }
        __syncthreads();
        s = (s == 2) ? 0 : s + 1;
        pf = (pf == 2) ? 0 : pf + 1;
    }

    // epilogue
#pragma unroll
    for (int mt = 0; mt < 4; ++mt) {
#pragma unroll
        for (int h = 0; h < 2; ++h) {
            const int row = row0 + wm * 64 + mt * 16 + g + h * 8;
            float* cr = C + (size_t)row * ldc;
#pragma unroll
            for (int nt = 0; nt < 4; ++nt) {
                const int col = col0 + wn * 32 + nt * 8 + tg * 2;
                if (col < N) {
                    float2 v;
                    v.x = apply_epi<EPI>(acc[mt][nt][h * 2 + 0], bias, col);
                    v.y = apply_epi<EPI>(acc[mt][nt][h * 2 + 1], bias, col + 1);
                    *reinterpret_cast<float2*>(cr + col) = v;
                }
            }
        }
    }
}

// ================= transpose + f16: out[c][r] = half(in[r][c]) =================
__global__ __launch_bounds__(256)
void transpose_h_kernel(const float* __restrict__ in, __half* __restrict__ out, int R, int Cc)
{
    __shared__ float t[32][33];
    const int r0 = blockIdx.y * 32, c0 = blockIdx.x * 32;
    const int tx = threadIdx.x, ty = threadIdx.y;
    for (int j = ty; j < 32; j += 8)
        if (r0 + j < R && c0 + tx < Cc)
            t[j][tx] = in[(size_t)(r0 + j) * Cc + c0 + tx];
    __syncthreads();
    for (int j = ty; j < 32; j += 8)
        if (c0 + j < Cc && r0 + tx < R)
            out[(size_t)(c0 + j) * R + r0 + tx] = __float2half(t[tx][j]);
}

// ================= float -> half pass (for x) =================
__global__ __launch_bounds__(256)
void f2h_kernel(const float* __restrict__ in, __half* __restrict__ out, int n4)
{
    for (int i = blockIdx.x * blockDim.x + threadIdx.x; i < n4; i += gridDim.x * blockDim.x) {
        float4 v = reinterpret_cast<const float4*>(in)[i];
        __half2 h0 = __floats2half2_rn(v.x, v.y);
        __half2 h1 = __floats2half2_rn(v.z, v.w);
        uint2 u;
        u.x = *reinterpret_cast<uint32_t*>(&h0);
        u.y = *reinterpret_cast<uint32_t*>(&h1);
        reinterpret_cast<uint2*>(out)[i] = u;
    }
}

// ================= xdbl[:, :64] -> half (dt GEMM A operand) =================
__global__ __launch_bounds__(256)
void dt2h_kernel(const float* __restrict__ in, __half* __restrict__ out)
{
    int idx = blockIdx.x * blockDim.x + threadIdx.x;   // over 8192*64
    int r = idx >> 6, c = idx & 63;
    out[idx] = __float2half(in[(size_t)r * XDBL_C + c]);
}

// ================= depthwise conv (k=4, SAME pad_lo=1) + SiLU =================
__global__ __launch_bounds__(256)
void conv_silu_kernel(int col_off, const float* __restrict__ w,
                      const float* __restrict__ bias,
                      float* __restrict__ outF, __half* __restrict__ outH,
                      int ldF, int ldH, int coloffH)
{
    __shared__ float tile[67][128];
    const int c_t = blockIdx.x, t_t = blockIdx.y, b = blockIdx.z;
    const int tx = threadIdx.x, ty = threadIdx.y;
    const int c = c_t * 128 + tx;
    const int t0 = t_t * 64;

    const float* src = g_xz + (size_t)b * LSEQ * DINNER + col_off + c;
    for (int r = ty; r < 67; r += 2) {
        int t = t0 + r - 1;
        tile[r][tx] = (t >= 0 && t < LSEQ) ? src[(size_t)t * DINNER] : 0.0f;
    }
    __syncthreads();

    const float w0 = w[c], w1 = w[DHALF + c], w2 = w[2 * DHALF + c], w3 = w[3 * DHALF + c];
    const float bb = bias[c];
    float*  dF = outF ? outF + (size_t)b * LSEQ * ldF + c : nullptr;
    __half* dH = outH ? outH + (size_t)b * LSEQ * ldH + coloffH + c : nullptr;
    for (int tt = ty; tt < 64; tt += 2) {
        float v = bb;
        v = fmaf(w0, tile[tt + 0][tx], v);
        v = fmaf(w1, tile[tt + 1][tx], v);
        v = fmaf(w2, tile[tt + 2][tx], v);
        v = fmaf(w3, tile[tt + 3][tx], v);
        float sv = __fdividef(v, 1.0f + __expf(-v));   // fast SiLU
        if (dF) dF[(size_t)(t0 + tt) * ldF] = sv;
        if (dH) dH[(size_t)(t0 + tt) * ldH] = __float2half(sv);
    }
}

// ================= selective scan (ILP-restructured reduction; bit-identical math) =================
__global__ __launch_bounds__(256)
void scan_kernel(const float* __restrict__ Dvec)
{
    const int grp = blockIdx.x * 16 + (threadIdx.x >> 4);
    const int n = threadIdx.x & 15;
    const int b = grp >> 10;
    const int d = grp & 1023;

    const float An = -(float)(n + 1);
    const float Dd = Dvec[d];

    const float* pD = g_delta + (size_t)b * LSEQ * DHALF + d;
    const float* pU = g_xs    + (size_t)b * LSEQ * DHALF + d;
    const float* pB = g_xdbl  + (size_t)b * LSEQ * XDBL_C + DTRANK + n;
    const float* pC = pB + DSTATE;
    __half*      pY = g_cath  + (size_t)b * LSEQ * DINNER + d;

    float h = 0.0f;
    for (int t0 = 0; t0 < LSEQ; t0 += 8) {
        float dv[8], uv[8], Bv[8], Cv[8], vv[8];
#pragma unroll
        for (int i = 0; i < 8; ++i) {
            dv[i] = pD[(size_t)(t0 + i) * DHALF];
            uv[i] = pU[(size_t)(t0 + i) * DHALF];
            Bv[i] = pB[(size_t)(t0 + i) * XDBL_C];
            Cv[i] = pC[(size_t)(t0 + i) * XDBL_C];
        }
        // serial h-chain (pure FFMA critical path; exp off-path)
#pragma unroll
        for (int i = 0; i < 8; ++i) {
            float dA = __expf(An * dv[i]);
            h = fmaf(dA, h, dv[i] * uv[i] * Bv[i]);
            vv[i] = h * Cv[i];
        }
        // butterfly reduction: 4 waves of 8 independent shfls (same op order per element)
#pragma unroll
        for (int off = 1; off < 16; off <<= 1) {
#pragma unroll
            for (int i = 0; i < 8; ++i)
                vv[i] += __shfl_xor_sync(0xffffffffu, vv[i], off);
        }
        if (n == 0) {
#pragma unroll
            for (int i = 0; i < 8; ++i)
                pY[(size_t)(t0 + i) * DINNER] = __float2half(fmaf(uv[i], Dd, vv[i]));
        }
    }
}

// ================= launch =================
extern "C" void kernel_launch(void* const* d_in, const int* in_sizes, int n_in,
                              void* d_out, int out_size)
{
    const float* x      = (const float*)d_in[0];
    const float* W_in   = (const float*)d_in[1];
    const float* cxw    = (const float*)d_in[2];
    const float* cxb    = (const float*)d_in[3];
    const float* czw    = (const float*)d_in[4];
    const float* czb    = (const float*)d_in[5];
    const float* W_xdbl = (const float*)d_in[6];
    const float* W_dt   = (const float*)d_in[7];
    const float* inv_dt = (const float*)d_in[8];
    const float* Dv     = (const float*)d_in[9];
    const float* W_out  = (const float*)d_in[10];
    const float* b_out  = (const float*)d_in[11];
    float* out = (float*)d_out;

    __half *xh, *xsh, *dth, *cath, *WinTh, *WxTh, *WdtTh, *WoutTh;
    float *xz, *xs, *xdbl, *delta;
    cudaGetSymbolAddress((void**)&xh,     g_xh);
    cudaGetSymbolAddress((void**)&xz,     g_xz);
    cudaGetSymbolAddress((void**)&xs,     g_xs);
    cudaGetSymbolAddress((void**)&xsh,    g_xsh);
    cudaGetSymbolAddress((void**)&xdbl,   g_xdbl);
    cudaGetSymbolAddress((void**)&dth,    g_dth);
    cudaGetSymbolAddress((void**)&delta,  g_delta);
    cudaGetSymbolAddress((void**)&cath,   g_cath);
    cudaGetSymbolAddress((void**)&WinTh,  g_WinTh);
    cudaGetSymbolAddress((void**)&WxTh,   g_WxTh);
    cudaGetSymbolAddress((void**)&WdtTh,  g_WdtTh);
    cudaGetSymbolAddress((void**)&WoutTh, g_WoutTh);

    cudaFuncSetAttribute((const void*)gemm_mma<0>, cudaFuncAttributeMaxDynamicSharedMemorySize, HSM_TOTAL);
    cudaFuncSetAttribute((const void*)gemm_mma<1>, cudaFuncAttributeMaxDynamicSharedMemorySize, HSM_TOTAL);
    cudaFuncSetAttribute((const void*)gemm_mma<2>, cudaFuncAttributeMaxDynamicSharedMemorySize, HSM_TOTAL);

    // 0) half(x); transpose+half weights -> [N][K] K-major
    f2h_kernel<<<2048, 256>>>(x, xh, MROWS * DMODEL / 4);
    transpose_h_kernel<<<dim3(DINNER / 32, DMODEL / 32), dim3(32, 8)>>>(W_in, WinTh, DMODEL, DINNER);
    transpose_h_kernel<<<dim3(XDBL_C / 32, DHALF / 32), dim3(32, 8)>>>(W_xdbl, WxTh, DHALF, XDBL_C);
    transpose_h_kernel<<<dim3(DHALF / 32, DTRANK / 32), dim3(32, 8)>>>(W_dt, WdtTh, DTRANK, DHALF);
    transpose_h_kernel<<<dim3(DMODEL / 32, DINNER / 32), dim3(32, 8)>>>(W_out, WoutTh, DINNER, DMODEL);

    // 1) xz = x @ W_in        (8192 x 2048, K=1024)
    gemm_mma<0><<<dim3(DINNER / 128, MROWS / 128), 256, HSM_TOTAL>>>(
        xh, WinTh, xz, nullptr, MROWS, DINNER, DMODEL, DMODEL, DMODEL, DINNER);

    // 2) depthwise conv + SiLU (xs -> float for scan + half for GEMM3; z -> half into cat)
    conv_silu_kernel<<<dim3(8, 32, 4), dim3(128, 2)>>>(0,     cxw, cxb, xs,      xsh,  DHALF,  DHALF,  0);
    conv_silu_kernel<<<dim3(8, 32, 4), dim3(128, 2)>>>(DHALF, czw, czb, nullptr, cath, 0,      DINNER, DHALF);

    // 3) x_dbl = xs @ W_xdbl  (8192 x 96, K=1024)
    gemm_mma<0><<<dim3(1, MROWS / 128), 256, HSM_TOTAL>>>(
        xsh, WxTh, xdbl, nullptr, MROWS, XDBL_C, DHALF, DHALF, DHALF, XDBL_C);

    // 3b) half copy of dt_low columns
    dt2h_kernel<<<MROWS * DTRANK / 256, 256>>>(xdbl, dth);

    // 4) delta = softplus(dt_low @ W_dt + 2*inv_dt)   (8192 x 1024, K=64)
    gemm_mma<2><<<dim3(DHALF / 128, MROWS / 128), 256, HSM_TOTAL>>>(
        dth, WdtTh, delta, inv_dt, MROWS, DHALF, DTRANK, DTRANK, DTRANK, DHALF);

    // 5) selective scan -> y (half) into g_cath[:, 0:1024]
    scan_kernel<<<256, 256>>>(Dv);

    // 6) out = [y | z] @ W_out + b_out   (8192 x 1024, K=2048)
    gemm_mma<1><<<dim3(DMODEL / 128, MROWS / 128), 256, HSM_TOTAL>>>(
        cath, WoutTh, out, b_out, MROWS, DMODEL, DINNER, DINNER, DINNER, DMODEL);
}

// round 15
// speedup vs baseline: 1.4590x; 1.4590x over previous
#include <cuda_runtime.h>
#include <cuda_fp16.h>
#include <cstdint>
#include <math.h>

#define B_SZ   4
#define LSEQ   2048
#define DMODEL 1024
#define DINNER 2048
#define DHALF  1024
#define DSTATE 16
#define DTRANK 64
#define XDBL_C 96
#define MROWS  (B_SZ * LSEQ)   // 8192

// ---------------- scratch (static device arrays; no allocation) ----------------
__device__ __half g_xh  [(size_t)MROWS * DMODEL];   // half(x)
__device__ float  g_xz  [(size_t)MROWS * DINNER];   // x @ W_in (float)
__device__ float  g_xsT [(size_t)DHALF * MROWS];    // silu(conv(xs)) CHAN-MAJOR [d][b*L+t]
__device__ __half g_xsh [(size_t)MROWS * DHALF];    // same, half row-major (GEMM3 A)
__device__ float  g_xdbl[(size_t)MROWS * XDBL_C];   // xs @ W_xdbl (float, scan B/C)
__device__ __half g_dth [(size_t)MROWS * DTRANK];   // half(xdbl[:, :64]) (dt GEMM A)
__device__ float  g_deltaT[(size_t)DHALF * MROWS];  // softplus(...) CHAN-MAJOR [d][b*L+t]
__device__ __half g_cath[(size_t)MROWS * DINNER];   // [y | z] half (GEMM4 A)
__device__ __half g_WinTh [(size_t)DINNER * DMODEL];
__device__ __half g_WxTh  [(size_t)XDBL_C * DHALF];
__device__ __half g_WdtTh [(size_t)DHALF * DTRANK];
__device__ __half g_WoutTh[(size_t)DMODEL * DINNER];

// ================= helpers =================
__device__ __forceinline__ uint32_t smem_u32(const void* p) {
    uint32_t a;
    asm("{ .reg .u64 t; cvta.to.shared.u64 t, %1; cvt.u32.u64 %0, t; }" : "=r"(a) : "l"(p));
    return a;
}
__device__ __forceinline__ void cp16(uint32_t dst, const void* src) {
    asm volatile("cp.async.cg.shared.global [%0], [%1], 16;" :: "r"(dst), "l"(src));
}
#define CP_COMMIT() asm volatile("cp.async.commit_group;" ::: "memory")
#define CP_WAIT(n)  asm volatile("cp.async.wait_group %0;" :: "n"(n) : "memory")

__device__ __forceinline__ void ldsm4(uint32_t* r, uint32_t addr) {
    asm volatile("ldmatrix.sync.aligned.m8n8.x4.shared.b16 {%0,%1,%2,%3}, [%4];"
        : "=r"(r[0]), "=r"(r[1]), "=r"(r[2]), "=r"(r[3]) : "r"(addr));
}
__device__ __forceinline__ void mma_f16(float* c, const uint32_t* a, uint32_t b0, uint32_t b1) {
    asm volatile(
        "mma.sync.aligned.m16n8k16.row.col.f32.f16.f16.f32 "
        "{%0,%1,%2,%3}, {%4,%5,%6,%7}, {%8,%9}, {%0,%1,%2,%3};"
        : "+f"(c[0]), "+f"(c[1]), "+f"(c[2]), "+f"(c[3])
        : "r"(a[0]), "r"(a[1]), "r"(a[2]), "r"(a[3]), "r"(b0), "r"(b1));
}

// ================= fp16 mma.sync GEMM =================
// C[M,N] = A[M,K] @ Bt[N,K]^T, half in, fp32 accum/out. CTA 128x128, BK=32,
// 256 thr, warp tile 64x32. 80B-padded smem rows; 3-stage cp.async.
// EPI 0: none; 1: +bias; 5: fast softplus(acc + 2*bias) stored TRANSPOSED into g_deltaT.
#define HSTAGE 10240
#define HSM_TOTAL (6 * HSTAGE)

template <int EPI>
__global__ __launch_bounds__(256)
void gemm_mma(const __half* __restrict__ A, const __half* __restrict__ Bt,
              float* __restrict__ C, const float* __restrict__ bias,
              int M, int N, int K, int lda, int ldb, int ldc)
{
    extern __shared__ char smc[];
    const uint32_t sAu = smem_u32(smc);
    const uint32_t sBu = sAu + 3 * HSTAGE;

    const int tid = threadIdx.x;
    const int wid = tid >> 5, lane = tid & 31;
    const int g = lane >> 2, tg = lane & 3;
    const int wm = wid & 1, wn = wid >> 1;      // 2 x 4 warp grid
    const int row0 = blockIdx.y * 128;
    const int col0 = blockIdx.x * 128;

    float acc[4][4][4];
#pragma unroll
    for (int i = 0; i < 4; ++i)
#pragma unroll
        for (int j = 0; j < 4; ++j)
#pragma unroll
            for (int c = 0; c < 4; ++c) acc[i][j][c] = 0.0f;

    const int rm = tid >> 2, cc = tid & 3;
    auto load_stage = [&](int s, int kt) {
        const uint32_t ab = sAu + s * HSTAGE;
        const uint32_t bb = sBu + s * HSTAGE;
        const int k0 = kt * 32;
#pragma unroll
        for (int i = 0; i < 2; ++i) {
            int m = rm + i * 64;
            cp16(ab + m * 80 + cc * 16, A + (size_t)(row0 + m) * lda + k0 + cc * 8);
        }
#pragma unroll
        for (int i = 0; i < 2; ++i) {
            int n = rm + i * 64;
            if (col0 + n < N)
                cp16(bb + n * 80 + cc * 16, Bt + (size_t)(col0 + n) * ldb + k0 + cc * 8);
        }
    };

    const int KT = K >> 5;   // >= 2 for all our GEMMs
    load_stage(0, 0); CP_COMMIT();
    load_stage(1, 1); CP_COMMIT();

    const int lrow = (lane & 7) + (lane & 8);
    const int lhi  = (lane >> 4) & 1;
    const uint32_t aoffs = (uint32_t)((wm * 64 + lrow) * 80 + lhi * 16);
    const uint32_t boffs = (uint32_t)((wn * 32 + lrow) * 80 + lhi * 16);

    int s = 0, pf = 2;
    for (int kt = 0; kt < KT; ++kt) {
        if (kt + 2 < KT)      { load_stage(pf, kt + 2); CP_COMMIT(); CP_WAIT(2); }
        else if (kt + 1 < KT) { CP_WAIT(1); }
        else                  { CP_WAIT(0); }
        __syncthreads();

        const uint32_t abase = sAu + s * HSTAGE + aoffs;
        const uint32_t bbase = sBu + s * HSTAGE + boffs;
#pragma unroll
        for (int ks = 0; ks < 2; ++ks) {
            uint32_t af[4][4], bf[2][4];
#pragma unroll
            for (int mt = 0; mt < 4; ++mt)
                ldsm4(af[mt], abase + mt * (16 * 80) + ks * 32);
#pragma unroll
            for (int pr = 0; pr < 2; ++pr)
                ldsm4(bf[pr], bbase + pr * (16 * 80) + ks * 32);
#pragma unroll
            for (int mt = 0; mt < 4; ++mt)
#pragma unroll
                for (int nt = 0; nt < 4; ++nt)
                    mma_f16(acc[mt][nt], af[mt], bf[nt >> 1][nt & 1], bf[nt >> 1][2 + (nt & 1)]);
        }
        __syncthreads();
        s = (s == 2) ? 0 : s + 1;
        pf = (pf == 2) ? 0 : pf + 1;
    }

    // epilogue
#pragma unroll
    for (int mt = 0; mt < 4; ++mt) {
#pragma unroll
        for (int h = 0; h < 2; ++h) {
            const int row = row0 + wm * 64 + mt * 16 + g + h * 8;
#pragma unroll
            for (int nt = 0; nt < 4; ++nt) {
                const int col = col0 + wn * 32 + nt * 8 + tg * 2;
                if (col < N) {
                    float2 v;
                    v.x = acc[mt][nt][h * 2 + 0];
                    v.y = acc[mt][nt][h * 2 + 1];
                    if (EPI == 1) { v.x += bias[col]; v.y += bias[col + 1]; }
                    if (EPI == 5) {
                        float a0 = v.x + 2.0f * bias[col];
                        float a1 = v.y + 2.0f * bias[col + 1];
                        a0 = fmaxf(a0, 0.0f) + __logf(1.0f + __expf(-fabsf(a0)));
                        a1 = fmaxf(a1, 0.0f) + __logf(1.0f + __expf(-fabsf(a1)));
                        g_deltaT[(size_t)col       * MROWS + row] = a0;   // transposed store
                        g_deltaT[(size_t)(col + 1) * MROWS + row] = a1;
                    } else {
                        float* cr = C + (size_t)row * ldc;
                        *reinterpret_cast<float2*>(cr + col) = v;
                    }
                }
            }
        }
    }
}

// ================= transpose + f16: out[c][r] = half(in[r][c]) =================
__global__ __launch_bounds__(256)
void transpose_h_kernel(const float* __restrict__ in, __half* __restrict__ out, int R, int Cc)
{
    __shared__ float t[32][33];
    const int r0 = blockIdx.y * 32, c0 = blockIdx.x * 32;
    const int tx = threadIdx.x, ty = threadIdx.y;
    for (int j = ty; j < 32; j += 8)
        if (r0 + j < R && c0 + tx < Cc)
            t[j][tx] = in[(size_t)(r0 + j) * Cc + c0 + tx];
    __syncthreads();
    for (int j = ty; j < 32; j += 8)
        if (c0 + j < Cc && r0 + tx < R)
            out[(size_t)(c0 + j) * R + r0 + tx] = __float2half(t[tx][j]);
}

// ================= float -> half pass (for x) =================
__global__ __launch_bounds__(256)
void f2h_kernel(const float* __restrict__ in, __half* __restrict__ out, int n4)
{
    for (int i = blockIdx.x * blockDim.x + threadIdx.x; i < n4; i += gridDim.x * blockDim.x) {
        float4 v = reinterpret_cast<const float4*>(in)[i];
        __half2 h0 = __floats2half2_rn(v.x, v.y);
        __half2 h1 = __floats2half2_rn(v.z, v.w);
        uint2 u;
        u.x = *reinterpret_cast<uint32_t*>(&h0);
        u.y = *reinterpret_cast<uint32_t*>(&h1);
        reinterpret_cast<uint2*>(out)[i] = u;
    }
}

// ================= xdbl[:, :64] -> half (dt GEMM A operand) =================
__global__ __launch_bounds__(256)
void dt2h_kernel(const float* __restrict__ in, __half* __restrict__ out)
{
    int idx = blockIdx.x * blockDim.x + threadIdx.x;   // over 8192*64
    int r = idx >> 6, c = idx & 63;
    out[idx] = __float2half(in[(size_t)r * XDBL_C + c]);
}

// ================= depthwise conv (k=4, SAME pad_lo=1) + SiLU =================
// Each thread computes 32 CONTIGUOUS t for one channel (tbase = ty*32), so the
// optional float chan-major output (xsT) is written as 8 coalesced float4 per thread.
__global__ __launch_bounds__(256)
void conv_silu_kernel(int col_off, const float* __restrict__ w,
                      const float* __restrict__ bias,
                      float* __restrict__ outT, __half* __restrict__ outH,
                      int ldH, int coloffH)
{
    __shared__ float tile[67][128];
    const int c_t = blockIdx.x, t_t = blockIdx.y, b = blockIdx.z;
    const int tx = threadIdx.x, ty = threadIdx.y;
    const int c = c_t * 128 + tx;
    const int t0 = t_t * 64;

    const float* src = g_xz + (size_t)b * LSEQ * DINNER + col_off + c;
    for (int r = ty; r < 67; r += 2) {
        int t = t0 + r - 1;
        tile[r][tx] = (t >= 0 && t < LSEQ) ? src[(size_t)t * DINNER] : 0.0f;
    }
    __syncthreads();

    const float w0 = w[c], w1 = w[DHALF + c], w2 = w[2 * DHALF + c], w3 = w[3 * DHALF + c];
    const float bb = bias[c];
    __half* dH = outH ? outH + (size_t)b * LSEQ * ldH + coloffH + c : nullptr;

    const int tbase = ty * 32;
    float rv[32];
#pragma unroll 8
    for (int i = 0; i < 32; ++i) {
        const int tt = tbase + i;
        float v = bb;
        v = fmaf(w0, tile[tt + 0][tx], v);
        v = fmaf(w1, tile[tt + 1][tx], v);
        v = fmaf(w2, tile[tt + 2][tx], v);
        v = fmaf(w3, tile[tt + 3][tx], v);
        float sv = __fdividef(v, 1.0f + __expf(-v));   // fast SiLU
        rv[i] = sv;
        if (dH) dH[(size_t)(t0 + tt) * ldH] = __float2half(sv);
    }
    if (outT) {
        float* dst = outT + (size_t)c * MROWS + (size_t)b * LSEQ + t0 + tbase;
#pragma unroll
        for (int i = 0; i < 8; ++i)
            reinterpret_cast<float4*>(dst)[i] =
                make_float4(rv[4 * i], rv[4 * i + 1], rv[4 * i + 2], rv[4 * i + 3]);
    }
}

// ================= selective scan (round-13 compute structure; coalesced loads) =================
__global__ __launch_bounds__(256)
void scan_kernel(const float* __restrict__ Dvec)
{
    const int grp = blockIdx.x * 16 + (threadIdx.x >> 4);
    const int n = threadIdx.x & 15;
    const int b = grp >> 10;
    const int d = grp & 1023;

    const float An = -(float)(n + 1);
    const float Dd = Dvec[d];

    const float* pDT = g_deltaT + (size_t)d * MROWS + (size_t)b * LSEQ;  // contiguous in t
    const float* pUT = g_xsT    + (size_t)d * MROWS + (size_t)b * LSEQ;  // contiguous in t
    const float* pB  = g_xdbl   + (size_t)b * LSEQ * XDBL_C + DTRANK + n;
    const float* pC  = pB + DSTATE;
    __half*      pY  = g_cath   + (size_t)b * LSEQ * DINNER + d;

    float h = 0.0f;
    for (int t0 = 0; t0 < LSEQ; t0 += 8) {
        float dv[8], uv[8], Bv[8], Cv[8];
        {
            float4 a0 = reinterpret_cast<const float4*>(pDT + t0)[0];
            float4 a1 = reinterpret_cast<const float4*>(pDT + t0)[1];
            dv[0] = a0.x; dv[1] = a0.y; dv[2] = a0.z; dv[3] = a0.w;
            dv[4] = a1.x; dv[5] = a1.y; dv[6] = a1.z; dv[7] = a1.w;
            float4 u0 = reinterpret_cast<const float4*>(pUT + t0)[0];
            float4 u1 = reinterpret_cast<const float4*>(pUT + t0)[1];
            uv[0] = u0.x; uv[1] = u0.y; uv[2] = u0.z; uv[3] = u0.w;
            uv[4] = u1.x; uv[5] = u1.y; uv[6] = u1.z; uv[7] = u1.w;
        }
#pragma unroll
        for (int i = 0; i < 8; ++i) {
            Bv[i] = pB[(size_t)(t0 + i) * XDBL_C];
            Cv[i] = pC[(size_t)(t0 + i) * XDBL_C];
        }
#pragma unroll
        for (int i = 0; i < 8; ++i) {
            float dA = __expf(An * dv[i]);
            h = fmaf(dA, h, dv[i] * uv[i] * Bv[i]);
            float v = h * Cv[i];
            v += __shfl_xor_sync(0xffffffffu, v, 1);
            v += __shfl_xor_sync(0xffffffffu, v, 2);
            v += __shfl_xor_sync(0xffffffffu, v, 4);
            v += __shfl_xor_sync(0xffffffffu, v, 8);
            if (n == 0) pY[(size_t)(t0 + i) * DINNER] = __float2half(fmaf(uv[i], Dd, v));
        }
    }
}

// ================= launch =================
extern "C" void kernel_launch(void* const* d_in, const int* in_sizes, int n_in,
                              void* d_out, int out_size)
{
    const float* x      = (const float*)d_in[0];
    const float* W_in   = (const float*)d_in[1];
    const float* cxw    = (const float*)d_in[2];
    const float* cxb    = (const float*)d_in[3];
    const float* czw    = (const float*)d_in[4];
    const float* czb    = (const float*)d_in[5];
    const float* W_xdbl = (const float*)d_in[6];
    const float* W_dt   = (const float*)d_in[7];
    const float* inv_dt = (const float*)d_in[8];
    const float* Dv     = (const float*)d_in[9];
    const float* W_out  = (const float*)d_in[10];
    const float* b_out  = (const float*)d_in[11];
    float* out = (float*)d_out;

    __half *xh, *xsh, *dth, *cath, *WinTh, *WxTh, *WdtTh, *WoutTh;
    float *xz, *xsT, *xdbl;
    cudaGetSymbolAddress((void**)&xh,     g_xh);
    cudaGetSymbolAddress((void**)&xz,     g_xz);
    cudaGetSymbolAddress((void**)&xsT,    g_xsT);
    cudaGetSymbolAddress((void**)&xsh,    g_xsh);
    cudaGetSymbolAddress((void**)&xdbl,   g_xdbl);
    cudaGetSymbolAddress((void**)&dth,    g_dth);
    cudaGetSymbolAddress((void**)&cath,   g_cath);
    cudaGetSymbolAddress((void**)&WinTh,  g_WinTh);
    cudaGetSymbolAddress((void**)&WxTh,   g_WxTh);
    cudaGetSymbolAddress((void**)&WdtTh,  g_WdtTh);
    cudaGetSymbolAddress((void**)&WoutTh, g_WoutTh);

    cudaFuncSetAttribute((const void*)gemm_mma<0>, cudaFuncAttributeMaxDynamicSharedMemorySize, HSM_TOTAL);
    cudaFuncSetAttribute((const void*)gemm_mma<1>, cudaFuncAttributeMaxDynamicSharedMemorySize, HSM_TOTAL);
    cudaFuncSetAttribute((const void*)gemm_mma<5>, cudaFuncAttributeMaxDynamicSharedMemorySize, HSM_TOTAL);

    // 0) half(x); transpose+half weights -> [N][K] K-major
    f2h_kernel<<<2048, 256>>>(x, xh, MROWS * DMODEL / 4);
    transpose_h_kernel<<<dim3(DINNER / 32, DMODEL / 32), dim3(32, 8)>>>(W_in, WinTh, DMODEL, DINNER);
    transpose_h_kernel<<<dim3(XDBL_C / 32, DHALF / 32), dim3(32, 8)>>>(W_xdbl, WxTh, DHALF, XDBL_C);
    transpose_h_kernel<<<dim3(DHALF / 32, DTRANK / 32), dim3(32, 8)>>>(W_dt, WdtTh, DTRANK, DHALF);
    transpose_h_kernel<<<dim3(DMODEL / 32, DINNER / 32), dim3(32, 8)>>>(W_out, WoutTh, DINNER, DMODEL);

    // 1) xz = x @ W_in        (8192 x 2048, K=1024)
    gemm_mma<0><<<dim3(DINNER / 128, MROWS / 128), 256, HSM_TOTAL>>>(
        xh, WinTh, xz, nullptr, MROWS, DINNER, DMODEL, DMODEL, DMODEL, DINNER);

    // 2) depthwise conv + SiLU (xs -> chan-major float for scan + half for GEMM3; z -> half into cat)
    conv_silu_kernel<<<dim3(8, 32, 4), dim3(128, 2)>>>(0,     cxw, cxb, xsT,     xsh,  DHALF,  0);
    conv_silu_kernel<<<dim3(8, 32, 4), dim3(128, 2)>>>(DHALF, czw, czb, nullptr, cath, DINNER, DHALF);

    // 3) x_dbl = xs @ W_xdbl  (8192 x 96, K=1024)
    gemm_mma<0><<<dim3(1, MROWS / 128), 256, HSM_TOTAL>>>(
        xsh, WxTh, xdbl, nullptr, MROWS, XDBL_C, DHALF, DHALF, DHALF, XDBL_C);

    // 3b) half copy of dt_low columns
    dt2h_kernel<<<MROWS * DTRANK / 256, 256>>>(xdbl, dth);

    // 4) deltaT = softplus(dt_low @ W_dt + 2*inv_dt), stored chan-major (8192 x 1024, K=64)
    gemm_mma<5><<<dim3(DHALF / 128, MROWS / 128), 256, HSM_TOTAL>>>(
        dth, WdtTh, nullptr, inv_dt, MROWS, DHALF, DTRANK, DTRANK, DTRANK, DHALF);

    // 5) selective scan -> y (half) into g_cath[:, 0:1024]
    scan_kernel<<<256, 256>>>(Dv);

    // 6) out = [y | z] @ W_out + b_out   (8192 x 1024, K=2048)
    gemm_mma<1><<<dim3(DMODEL / 128, MROWS / 128), 256, HSM_TOTAL>>>(
        cath, WoutTh, out, b_out, MROWS, DMODEL, DINNER, DINNER, DINNER, DMODEL);
}